// round 1
// baseline (speedup 1.0000x reference)
#include <cuda_runtime.h>
#include <math.h>

// Problem constants
#define S_TOK   8192
#define HDIM    1024
#define NHEAD   16
#define HD      64
#define MLPD    4096
#define NSEG    8
#define LSEG    1024

// Scratch buffers (static device arrays; no allocation allowed)
__device__ float g_h   [S_TOK * HDIM];   // ln0 out
__device__ float g_qkv [S_TOK * 3 * HDIM];
__device__ float g_attn[S_TOK * HDIM];
__device__ float g_x1  [S_TOK * HDIM];   // x + attn@wo^T
__device__ float g_h2  [S_TOK * HDIM];   // ln1 out
__device__ float g_mid [S_TOK * MLPD];   // gelu(fc0)

// ---------------------------------------------------------------------------
// LayerNorm: one block per row (1024 elems), 256 threads, float4
// ---------------------------------------------------------------------------
__global__ void __launch_bounds__(256) ln_kernel(const float* __restrict__ x,
                                                 const float* __restrict__ g,
                                                 const float* __restrict__ b,
                                                 float* __restrict__ out)
{
    int row = blockIdx.x;
    int t = threadIdx.x;
    const float4* xr = (const float4*)(x + (size_t)row * HDIM);
    float4 xv = xr[t];
    float s  = xv.x + xv.y + xv.z + xv.w;
    float ss = xv.x*xv.x + xv.y*xv.y + xv.z*xv.z + xv.w*xv.w;
    #pragma unroll
    for (int o = 16; o > 0; o >>= 1) {
        s  += __shfl_xor_sync(0xffffffffu, s,  o);
        ss += __shfl_xor_sync(0xffffffffu, ss, o);
    }
    __shared__ float sred[8], ssred[8];
    if ((t & 31) == 0) { sred[t >> 5] = s; ssred[t >> 5] = ss; }
    __syncthreads();
    if (t < 32) {
        float a  = (t < 8) ? sred[t]  : 0.f;
        float a2 = (t < 8) ? ssred[t] : 0.f;
        #pragma unroll
        for (int o = 4; o > 0; o >>= 1) {
            a  += __shfl_xor_sync(0xffffffffu, a,  o);
            a2 += __shfl_xor_sync(0xffffffffu, a2, o);
        }
        if (t == 0) { sred[0] = a; ssred[0] = a2; }
    }
    __syncthreads();
    float mean = sred[0] * (1.f / HDIM);
    float var  = ssred[0] * (1.f / HDIM) - mean * mean;
    float rstd = rsqrtf(var + 1e-5f);
    float4 gv = ((const float4*)g)[t];
    float4 bv = ((const float4*)b)[t];
    float4 ov;
    ov.x = (xv.x - mean) * rstd * gv.x + bv.x;
    ov.y = (xv.y - mean) * rstd * gv.y + bv.y;
    ov.z = (xv.z - mean) * rstd * gv.z + bv.z;
    ov.w = (xv.w - mean) * rstd * gv.w + bv.w;
    ((float4*)(out + (size_t)row * HDIM))[t] = ov;
}

// ---------------------------------------------------------------------------
// NT SGEMM: C[M,N] = A[M,K] @ B[N,K]^T  (+ epilogue)
// 128x128 block tile, BK=16, 256 threads, 8x8 per thread.
// EPI: 0=none, 1=+res, 2=+bias then GELU(exact), 3=+bias+res
// ---------------------------------------------------------------------------
template <int EPI>
__global__ void __launch_bounds__(256) sgemm_nt(const float* __restrict__ A,
                                                const float* __restrict__ B,
                                                float* __restrict__ C,
                                                const float* __restrict__ bias,
                                                const float* __restrict__ res,
                                                int M, int N, int K)
{
    __shared__ float As[16][128];
    __shared__ float Bs[16][128];
    const int tid = threadIdx.x;
    const int tx = tid & 15;
    const int ty = tid >> 4;

    const float* Ab = A + (size_t)blockIdx.y * 128 * K;
    const float* Bb = B + (size_t)blockIdx.x * 128 * K;

    float acc[8][8];
    #pragma unroll
    for (int i = 0; i < 8; i++)
        #pragma unroll
        for (int j = 0; j < 8; j++) acc[i][j] = 0.f;

    const int lr = tid >> 2;          // 0..63
    const int lc = (tid & 3) * 4;     // 0,4,8,12

    for (int k0 = 0; k0 < K; k0 += 16) {
        #pragma unroll
        for (int i = 0; i < 2; i++) {
            int r = lr + i * 64;
            float4 va = *(const float4*)(Ab + (size_t)r * K + k0 + lc);
            As[lc + 0][r] = va.x; As[lc + 1][r] = va.y;
            As[lc + 2][r] = va.z; As[lc + 3][r] = va.w;
            float4 vb = *(const float4*)(Bb + (size_t)r * K + k0 + lc);
            Bs[lc + 0][r] = vb.x; Bs[lc + 1][r] = vb.y;
            Bs[lc + 2][r] = vb.z; Bs[lc + 3][r] = vb.w;
        }
        __syncthreads();
        #pragma unroll
        for (int kk = 0; kk < 16; kk++) {
            float ra[8], rb[8];
            *(float4*)&ra[0] = *(const float4*)&As[kk][ty * 4];
            *(float4*)&ra[4] = *(const float4*)&As[kk][64 + ty * 4];
            *(float4*)&rb[0] = *(const float4*)&Bs[kk][tx * 4];
            *(float4*)&rb[4] = *(const float4*)&Bs[kk][64 + tx * 4];
            #pragma unroll
            for (int i = 0; i < 8; i++)
                #pragma unroll
                for (int j = 0; j < 8; j++)
                    acc[i][j] += ra[i] * rb[j];
        }
        __syncthreads();
    }

    #pragma unroll
    for (int i = 0; i < 8; i++) {
        int row = blockIdx.y * 128 + ((i < 4) ? (ty * 4 + i) : (64 + ty * 4 + i - 4));
        #pragma unroll
        for (int j = 0; j < 8; j++) {
            int col = blockIdx.x * 128 + ((j < 4) ? (tx * 4 + j) : (64 + tx * 4 + j - 4));
            float v = acc[i][j];
            if (EPI == 2 || EPI == 3) v += bias[col];
            if (EPI == 2) v = 0.5f * v * (1.f + erff(v * 0.70710678118f));
            if (EPI == 1 || EPI == 3) v += res[(size_t)row * N + col];
            C[(size_t)row * N + col] = v;
        }
    }
}

// ---------------------------------------------------------------------------
// RoPE on q and k halves of qkv, in place.
// qkv row layout: [q(16x64) | k(16x64) | v(16x64)]; pair i uses cos/sin[s*32+i]
// ---------------------------------------------------------------------------
__global__ void __launch_bounds__(256) rope_kernel(float* __restrict__ qkv,
                                                   const float* __restrict__ cosb,
                                                   const float* __restrict__ sinb)
{
    int idx = blockIdx.x * blockDim.x + threadIdx.x;  // 8192*2*16*32 threads
    int i    = idx & 31;
    int head = (idx >> 5) & 15;
    int qk   = (idx >> 9) & 1;
    int s    = idx >> 10;
    float c  = cosb[s * 32 + i];
    float sn = sinb[s * 32 + i];
    float2* p = (float2*)(qkv + (size_t)s * 3072 + qk * 1024 + head * 64 + 2 * i);
    float2 v = *p;
    float2 o;
    o.x = v.x * c - v.y * sn;
    o.y = v.x * sn + v.y * c;
    *p = o;
}

// ---------------------------------------------------------------------------
// Attention (flash-style, online softmax), fp32.
// grid (L/128, NH, NSEG), 128 threads; thread t owns query row (qt*128+t).
// ---------------------------------------------------------------------------
__global__ void __launch_bounds__(128) attn_kernel(const float* __restrict__ qkv,
                                                   float* __restrict__ out)
{
    const int qt   = blockIdx.x;
    const int head = blockIdx.y;
    const int seg  = blockIdx.z;
    const int t    = threadIdx.x;
    const int qrow = seg * LSEG + qt * 128 + t;

    float q[64];
    const float* qp = qkv + (size_t)qrow * 3072 + head * 64;
    #pragma unroll
    for (int d4 = 0; d4 < 16; d4++)
        *(float4*)&q[d4 * 4] = *(const float4*)(qp + d4 * 4);

    float acc[64];
    #pragma unroll
    for (int d = 0; d < 64; d++) acc[d] = 0.f;
    float m = -1e30f, l = 0.f;

    __shared__ float Ks[32][64];
    __shared__ float Vs[32][64];
    const float* kbase = qkv + (size_t)seg * LSEG * 3072 + 1024 + head * 64;
    const float* vbase = kbase + 1024;

    for (int kt = 0; kt < 32; kt++) {
        __syncthreads();
        #pragma unroll
        for (int i = 0; i < 4; i++) {
            int e = t + i * 128;      // float4 index 0..511
            int r = e >> 4;           // 16 float4 per 64-wide row
            int c = (e & 15) * 4;
            *(float4*)&Ks[r][c] = *(const float4*)(kbase + (size_t)(kt * 32 + r) * 3072 + c);
            *(float4*)&Vs[r][c] = *(const float4*)(vbase + (size_t)(kt * 32 + r) * 3072 + c);
        }
        __syncthreads();

        float sc[32];
        float tmax = -1e30f;
        #pragma unroll
        for (int j = 0; j < 32; j++) {
            float s = 0.f;
            #pragma unroll
            for (int d = 0; d < 64; d++) s += q[d] * Ks[j][d];
            s *= 0.125f;   // 1/sqrt(64)
            sc[j] = s;
            tmax = fmaxf(tmax, s);
        }
        float mnew = fmaxf(m, tmax);
        float corr = __expf(m - mnew);
        l *= corr;
        #pragma unroll
        for (int d = 0; d < 64; d++) acc[d] *= corr;
        #pragma unroll
        for (int j = 0; j < 32; j++) {
            float p = __expf(sc[j] - mnew);
            l += p;
            #pragma unroll
            for (int d = 0; d < 64; d++) acc[d] += p * Vs[j][d];
        }
        m = mnew;
    }

    float inv = 1.f / l;
    float* op = out + (size_t)qrow * HDIM + head * 64;
    #pragma unroll
    for (int d = 0; d < 64; d++) op[d] = acc[d] * inv;
}

// ---------------------------------------------------------------------------
extern "C" void kernel_launch(void* const* d_in, const int* in_sizes, int n_in,
                              void* d_out, int out_size)
{
    const float* x        = (const float*)d_in[0];
    const float* wqkv     = (const float*)d_in[1];
    const float* wo       = (const float*)d_in[2];
    const float* ln0_g    = (const float*)d_in[3];
    const float* ln0_b    = (const float*)d_in[4];
    const float* ln1_g    = (const float*)d_in[5];
    const float* ln1_b    = (const float*)d_in[6];
    const float* fc0_w    = (const float*)d_in[7];
    const float* fc0_b    = (const float*)d_in[8];
    const float* fc1_w    = (const float*)d_in[9];
    const float* fc1_b    = (const float*)d_in[10];
    const float* rope_cos = (const float*)d_in[11];
    const float* rope_sin = (const float*)d_in[12];
    float* out = (float*)d_out;

    float *h, *qkv, *attn, *x1, *h2, *mid;
    cudaGetSymbolAddress((void**)&h,    g_h);
    cudaGetSymbolAddress((void**)&qkv,  g_qkv);
    cudaGetSymbolAddress((void**)&attn, g_attn);
    cudaGetSymbolAddress((void**)&x1,   g_x1);
    cudaGetSymbolAddress((void**)&h2,   g_h2);
    cudaGetSymbolAddress((void**)&mid,  g_mid);

    // 1. ln0
    ln_kernel<<<S_TOK, 256>>>(x, ln0_g, ln0_b, h);
    // 2. qkv = h @ wqkv^T        [8192,3072,1024]
    sgemm_nt<0><<<dim3(3 * HDIM / 128, S_TOK / 128), 256>>>(h, wqkv, qkv, nullptr, nullptr,
                                                            S_TOK, 3 * HDIM, HDIM);
    // 3. rope(q), rope(k)
    rope_kernel<<<(S_TOK * 2 * NHEAD * 32) / 256, 256>>>(qkv, rope_cos, rope_sin);
    // 4. attention
    attn_kernel<<<dim3(LSEG / 128, NHEAD, NSEG), 128>>>(qkv, attn);
    // 5. x1 = x + attn @ wo^T    [8192,1024,1024]
    sgemm_nt<1><<<dim3(HDIM / 128, S_TOK / 128), 256>>>(attn, wo, x1, nullptr, x,
                                                        S_TOK, HDIM, HDIM);
    // 6. ln1
    ln_kernel<<<S_TOK, 256>>>(x1, ln1_g, ln1_b, h2);
    // 7. mid = gelu(h2 @ fc0_w^T + b)   [8192,4096,1024]
    sgemm_nt<2><<<dim3(MLPD / 128, S_TOK / 128), 256>>>(h2, fc0_w, mid, fc0_b, nullptr,
                                                        S_TOK, MLPD, HDIM);
    // 8. out = x1 + mid @ fc1_w^T + b   [8192,1024,4096]
    sgemm_nt<3><<<dim3(HDIM / 128, S_TOK / 128), 256>>>(mid, fc1_w, out, fc1_b, x1,
                                                        S_TOK, HDIM, MLPD);
}

// round 3
// speedup vs baseline: 1.9673x; 1.9673x over previous
#include <cuda_runtime.h>
#include <math.h>
#include <stdint.h>

// Problem constants
#define S_TOK   8192
#define HDIM    1024
#define NHEAD   16
#define HD      64
#define MLPD    4096
#define NSEG    8
#define LSEG    1024

// Scratch buffers (static device arrays; no allocation allowed)
__device__ float g_h   [S_TOK * HDIM];   // ln0 out
__device__ float g_qkv [S_TOK * 3 * HDIM];
__device__ float g_attn[S_TOK * HDIM];
__device__ float g_x1  [S_TOK * HDIM];   // x + attn@wo^T
__device__ float g_h2  [S_TOK * HDIM];   // ln1 out
__device__ float g_mid [S_TOK * MLPD];   // gelu(fc0)

__device__ __forceinline__ uint32_t f2tf(float x) {
    uint32_t r;
    asm("cvt.rna.tf32.f32 %0, %1;" : "=r"(r) : "f"(x));
    return r;
}

__device__ __forceinline__ void mma_tf32(float* d, const uint32_t* a, const uint32_t* b) {
    asm volatile(
        "mma.sync.aligned.m16n8k8.row.col.f32.tf32.tf32.f32 "
        "{%0,%1,%2,%3}, {%4,%5,%6,%7}, {%8,%9}, {%0,%1,%2,%3};"
        : "+f"(d[0]), "+f"(d[1]), "+f"(d[2]), "+f"(d[3])
        : "r"(a[0]), "r"(a[1]), "r"(a[2]), "r"(a[3]), "r"(b[0]), "r"(b[1]));
}

// ---------------------------------------------------------------------------
// tf32 mma.sync GEMM: C[M,N] = A[M,K] @ B[N,K]^T (+ epilogue)
// 128x128 block tile, BK=32, 256 threads (8 warps, 2x4), 64x32 warp tile.
// EPI: 0=none, 1=+res, 2=+bias then GELU(exact), 3=+bias+res
// ---------------------------------------------------------------------------
#define BK  32
#define PAD 4

template <int EPI>
__global__ void __launch_bounds__(256) tc_gemm(const float* __restrict__ A,
                                               const float* __restrict__ B,
                                               float* __restrict__ C,
                                               const float* __restrict__ bias,
                                               const float* __restrict__ res,
                                               int M, int N, int K)
{
    __shared__ uint32_t As[128][BK + PAD];
    __shared__ uint32_t Bs[128][BK + PAD];

    const int tid  = threadIdx.x;
    const int wid  = tid >> 5;
    const int lane = tid & 31;
    const int warp_m = wid >> 2;   // 0..1
    const int warp_n = wid & 3;    // 0..3
    const int lr = lane >> 2;      // 0..7
    const int lc = lane & 3;       // 0..3

    const float* Ab = A + (size_t)blockIdx.y * 128 * K;
    const float* Bb = B + (size_t)blockIdx.x * 128 * K;

    // loader indices: 4 float4 each from A and B per chunk
    const int ldrow = tid >> 1;          // 0..127
    const int ldc4  = (tid & 1) * 16;    // 0 or 16 (float offset, 2 float4 each)

    float acc[16][4];
    #pragma unroll
    for (int i = 0; i < 16; i++)
        #pragma unroll
        for (int j = 0; j < 4; j++) acc[i][j] = 0.f;

    const int NC = K / BK;
    float4 pa[4], pb[4];

    // prefetch chunk 0: each thread: rows ldrow, 2x float4 at ldc4, ldc4+... plus second row set
    // Layout: thread covers (ldrow, ldc4..ldc4+7) via 2 float4 → need 4 float4 to cover
    // 128x32 with 256 threads: 1024 float4 / 256 = 4 each.
    // f = i*256 + tid; row = f >> 3; c4 = (f & 7) * 4
    #pragma unroll
    for (int i = 0; i < 4; i++) {
        int f = i * 256 + tid;
        int row = f >> 3, c4 = (f & 7) * 4;
        pa[i] = *(const float4*)(Ab + (size_t)row * K + c4);
        pb[i] = *(const float4*)(Bb + (size_t)row * K + c4);
    }

    for (int c = 0; c < NC; c++) {
        // store prefetched chunk to smem (tf32 convert)
        #pragma unroll
        for (int i = 0; i < 4; i++) {
            int f = i * 256 + tid;
            int row = f >> 3, c4 = (f & 7) * 4;
            As[row][c4 + 0] = f2tf(pa[i].x); As[row][c4 + 1] = f2tf(pa[i].y);
            As[row][c4 + 2] = f2tf(pa[i].z); As[row][c4 + 3] = f2tf(pa[i].w);
            Bs[row][c4 + 0] = f2tf(pb[i].x); Bs[row][c4 + 1] = f2tf(pb[i].y);
            Bs[row][c4 + 2] = f2tf(pb[i].z); Bs[row][c4 + 3] = f2tf(pb[i].w);
        }
        __syncthreads();

        if (c + 1 < NC) {
            const int k0 = (c + 1) * BK;
            #pragma unroll
            for (int i = 0; i < 4; i++) {
                int f = i * 256 + tid;
                int row = f >> 3, c4 = (f & 7) * 4;
                pa[i] = *(const float4*)(Ab + (size_t)row * K + k0 + c4);
                pb[i] = *(const float4*)(Bb + (size_t)row * K + k0 + c4);
            }
        }

        #pragma unroll
        for (int kk = 0; kk < BK; kk += 8) {
            uint32_t afr[4][4], bfr[4][2];
            #pragma unroll
            for (int mt = 0; mt < 4; mt++) {
                int ar = warp_m * 64 + mt * 16 + lr;
                afr[mt][0] = As[ar][kk + lc];
                afr[mt][1] = As[ar + 8][kk + lc];
                afr[mt][2] = As[ar][kk + lc + 4];
                afr[mt][3] = As[ar + 8][kk + lc + 4];
            }
            #pragma unroll
            for (int nt = 0; nt < 4; nt++) {
                int br = warp_n * 32 + nt * 8 + lr;
                bfr[nt][0] = Bs[br][kk + lc];
                bfr[nt][1] = Bs[br][kk + lc + 4];
            }
            #pragma unroll
            for (int mt = 0; mt < 4; mt++)
                #pragma unroll
                for (int nt = 0; nt < 4; nt++)
                    mma_tf32(acc[mt * 4 + nt], afr[mt], bfr[nt]);
        }
        __syncthreads();
    }

    // Epilogue: fragment (mt, nt): rows base + lr (+8), cols base + lc*2 (+1)
    #pragma unroll
    for (int mt = 0; mt < 4; mt++) {
        #pragma unroll
        for (int h = 0; h < 2; h++) {
            int row = blockIdx.y * 128 + warp_m * 64 + mt * 16 + lr + h * 8;
            float* Crow = C + (size_t)row * N;
            const float* Rrow = (EPI == 1 || EPI == 3) ? res + (size_t)row * N : nullptr;
            #pragma unroll
            for (int nt = 0; nt < 4; nt++) {
                int col = blockIdx.x * 128 + warp_n * 32 + nt * 8 + lc * 2;
                float v0 = acc[mt * 4 + nt][h * 2 + 0];
                float v1 = acc[mt * 4 + nt][h * 2 + 1];
                if (EPI == 2 || EPI == 3) {
                    v0 += bias[col];
                    v1 += bias[col + 1];
                }
                if (EPI == 2) {
                    v0 = 0.5f * v0 * (1.f + erff(v0 * 0.70710678118f));
                    v1 = 0.5f * v1 * (1.f + erff(v1 * 0.70710678118f));
                }
                if (EPI == 1 || EPI == 3) {
                    v0 += Rrow[col];
                    v1 += Rrow[col + 1];
                }
                *(float2*)(Crow + col) = make_float2(v0, v1);
            }
        }
    }
}

// ---------------------------------------------------------------------------
// LayerNorm: one block per row (1024 elems), 256 threads, float4
// ---------------------------------------------------------------------------
__global__ void __launch_bounds__(256) ln_kernel(const float* __restrict__ x,
                                                 const float* __restrict__ g,
                                                 const float* __restrict__ b,
                                                 float* __restrict__ out)
{
    int row = blockIdx.x;
    int t = threadIdx.x;
    const float4* xr = (const float4*)(x + (size_t)row * HDIM);
    float4 xv = xr[t];
    float s  = xv.x + xv.y + xv.z + xv.w;
    float ss = xv.x*xv.x + xv.y*xv.y + xv.z*xv.z + xv.w*xv.w;
    #pragma unroll
    for (int o = 16; o > 0; o >>= 1) {
        s  += __shfl_xor_sync(0xffffffffu, s,  o);
        ss += __shfl_xor_sync(0xffffffffu, ss, o);
    }
    __shared__ float sred[8], ssred[8];
    if ((t & 31) == 0) { sred[t >> 5] = s; ssred[t >> 5] = ss; }
    __syncthreads();
    if (t < 32) {
        float a  = (t < 8) ? sred[t]  : 0.f;
        float a2 = (t < 8) ? ssred[t] : 0.f;
        #pragma unroll
        for (int o = 4; o > 0; o >>= 1) {
            a  += __shfl_xor_sync(0xffffffffu, a,  o);
            a2 += __shfl_xor_sync(0xffffffffu, a2, o);
        }
        if (t == 0) { sred[0] = a; ssred[0] = a2; }
    }
    __syncthreads();
    float mean = sred[0] * (1.f / HDIM);
    float var  = ssred[0] * (1.f / HDIM) - mean * mean;
    float rstd = rsqrtf(var + 1e-5f);
    float4 gv = ((const float4*)g)[t];
    float4 bv = ((const float4*)b)[t];
    float4 ov;
    ov.x = (xv.x - mean) * rstd * gv.x + bv.x;
    ov.y = (xv.y - mean) * rstd * gv.y + bv.y;
    ov.z = (xv.z - mean) * rstd * gv.z + bv.z;
    ov.w = (xv.w - mean) * rstd * gv.w + bv.w;
    ((float4*)(out + (size_t)row * HDIM))[t] = ov;
}

// ---------------------------------------------------------------------------
// RoPE on q and k halves of qkv, in place.
// ---------------------------------------------------------------------------
__global__ void __launch_bounds__(256) rope_kernel(float* __restrict__ qkv,
                                                   const float* __restrict__ cosb,
                                                   const float* __restrict__ sinb)
{
    int idx = blockIdx.x * blockDim.x + threadIdx.x;
    int i    = idx & 31;
    int head = (idx >> 5) & 15;
    int qk   = (idx >> 9) & 1;
    int s    = idx >> 10;
    float c  = cosb[s * 32 + i];
    float sn = sinb[s * 32 + i];
    float2* p = (float2*)(qkv + (size_t)s * 3072 + qk * 1024 + head * 64 + 2 * i);
    float2 v = *p;
    float2 o;
    o.x = v.x * c - v.y * sn;
    o.y = v.x * sn + v.y * c;
    *p = o;
}

// ---------------------------------------------------------------------------
// Attention (flash-style, online softmax), fp32.
// ---------------------------------------------------------------------------
__global__ void __launch_bounds__(128) attn_kernel(const float* __restrict__ qkv,
                                                   float* __restrict__ out)
{
    const int qt   = blockIdx.x;
    const int head = blockIdx.y;
    const int seg  = blockIdx.z;
    const int t    = threadIdx.x;
    const int qrow = seg * LSEG + qt * 128 + t;

    float q[64];
    const float* qp = qkv + (size_t)qrow * 3072 + head * 64;
    #pragma unroll
    for (int d4 = 0; d4 < 16; d4++)
        *(float4*)&q[d4 * 4] = *(const float4*)(qp + d4 * 4);

    float acc[64];
    #pragma unroll
    for (int d = 0; d < 64; d++) acc[d] = 0.f;
    float m = -1e30f, l = 0.f;

    __shared__ float Ks[32][64];
    __shared__ float Vs[32][64];
    const float* kbase = qkv + (size_t)seg * LSEG * 3072 + 1024 + head * 64;
    const float* vbase = kbase + 1024;

    for (int kt = 0; kt < 32; kt++) {
        __syncthreads();
        #pragma unroll
        for (int i = 0; i < 4; i++) {
            int e = t + i * 128;
            int r = e >> 4;
            int c = (e & 15) * 4;
            *(float4*)&Ks[r][c] = *(const float4*)(kbase + (size_t)(kt * 32 + r) * 3072 + c);
            *(float4*)&Vs[r][c] = *(const float4*)(vbase + (size_t)(kt * 32 + r) * 3072 + c);
        }
        __syncthreads();

        float sc[32];
        float tmax = -1e30f;
        #pragma unroll
        for (int j = 0; j < 32; j++) {
            float s = 0.f;
            #pragma unroll
            for (int d = 0; d < 64; d++) s += q[d] * Ks[j][d];
            s *= 0.125f;
            sc[j] = s;
            tmax = fmaxf(tmax, s);
        }
        float mnew = fmaxf(m, tmax);
        float corr = __expf(m - mnew);
        l *= corr;
        #pragma unroll
        for (int d = 0; d < 64; d++) acc[d] *= corr;
        #pragma unroll
        for (int j = 0; j < 32; j++) {
            float p = __expf(sc[j] - mnew);
            l += p;
            #pragma unroll
            for (int d = 0; d < 64; d++) acc[d] += p * Vs[j][d];
        }
        m = mnew;
    }

    float inv = 1.f / l;
    float* op = out + (size_t)qrow * HDIM + head * 64;
    #pragma unroll
    for (int d = 0; d < 64; d++) op[d] = acc[d] * inv;
}

// ---------------------------------------------------------------------------
extern "C" void kernel_launch(void* const* d_in, const int* in_sizes, int n_in,
                              void* d_out, int out_size)
{
    const float* x        = (const float*)d_in[0];
    const float* wqkv     = (const float*)d_in[1];
    const float* wo       = (const float*)d_in[2];
    const float* ln0_g    = (const float*)d_in[3];
    const float* ln0_b    = (const float*)d_in[4];
    const float* ln1_g    = (const float*)d_in[5];
    const float* ln1_b    = (const float*)d_in[6];
    const float* fc0_w    = (const float*)d_in[7];
    const float* fc0_b    = (const float*)d_in[8];
    const float* fc1_w    = (const float*)d_in[9];
    const float* fc1_b    = (const float*)d_in[10];
    const float* rope_cos = (const float*)d_in[11];
    const float* rope_sin = (const float*)d_in[12];
    float* out = (float*)d_out;

    float *h, *qkv, *attn, *x1, *h2, *mid;
    cudaGetSymbolAddress((void**)&h,    g_h);
    cudaGetSymbolAddress((void**)&qkv,  g_qkv);
    cudaGetSymbolAddress((void**)&attn, g_attn);
    cudaGetSymbolAddress((void**)&x1,   g_x1);
    cudaGetSymbolAddress((void**)&h2,   g_h2);
    cudaGetSymbolAddress((void**)&mid,  g_mid);

    // 1. ln0
    ln_kernel<<<S_TOK, 256>>>(x, ln0_g, ln0_b, h);
    // 2. qkv = h @ wqkv^T        [8192,3072,1024]
    tc_gemm<0><<<dim3(3 * HDIM / 128, S_TOK / 128), 256>>>(h, wqkv, qkv, nullptr, nullptr,
                                                           S_TOK, 3 * HDIM, HDIM);
    // 3. rope(q), rope(k)
    rope_kernel<<<(S_TOK * 2 * NHEAD * 32) / 256, 256>>>(qkv, rope_cos, rope_sin);
    // 4. attention
    attn_kernel<<<dim3(LSEG / 128, NHEAD, NSEG), 128>>>(qkv, attn);
    // 5. x1 = x + attn @ wo^T    [8192,1024,1024]
    tc_gemm<1><<<dim3(HDIM / 128, S_TOK / 128), 256>>>(attn, wo, x1, nullptr, x,
                                                       S_TOK, HDIM, HDIM);
    // 6. ln1
    ln_kernel<<<S_TOK, 256>>>(x1, ln1_g, ln1_b, h2);
    // 7. mid = gelu(h2 @ fc0_w^T + b)   [8192,4096,1024]
    tc_gemm<2><<<dim3(MLPD / 128, S_TOK / 128), 256>>>(h2, fc0_w, mid, fc0_b, nullptr,
                                                       S_TOK, MLPD, HDIM);
    // 8. out = x1 + mid @ fc1_w^T + b   [8192,1024,4096]
    tc_gemm<3><<<dim3(HDIM / 128, S_TOK / 128), 256>>>(mid, fc1_w, out, fc1_b, x1,
                                                       S_TOK, HDIM, MLPD);
}

// round 4
// speedup vs baseline: 2.8069x; 1.4267x over previous
#include <cuda_runtime.h>
#include <math.h>
#include <stdint.h>

// Problem constants
#define S_TOK   8192
#define HDIM    1024
#define NHEAD   16
#define HD      64
#define MLPD    4096
#define NSEG    8
#define LSEG    1024

// Scratch buffers
__device__ float g_h   [S_TOK * HDIM];
__device__ float g_qkv [S_TOK * 3 * HDIM];
__device__ float g_attn[S_TOK * HDIM];
__device__ float g_x1  [S_TOK * HDIM];
__device__ float g_h2  [S_TOK * HDIM];
__device__ float g_mid [S_TOK * MLPD];

__device__ __forceinline__ uint32_t f2tf(float x) {
    uint32_t r;
    asm("cvt.rna.tf32.f32 %0, %1;" : "=r"(r) : "f"(x));
    return r;
}

__device__ __forceinline__ void mma_tf32(float* d, const uint32_t* a, const uint32_t* b) {
    asm volatile(
        "mma.sync.aligned.m16n8k8.row.col.f32.tf32.tf32.f32 "
        "{%0,%1,%2,%3}, {%4,%5,%6,%7}, {%8,%9}, {%0,%1,%2,%3};"
        : "+f"(d[0]), "+f"(d[1]), "+f"(d[2]), "+f"(d[3])
        : "r"(a[0]), "r"(a[1]), "r"(a[2]), "r"(a[3]), "r"(b[0]), "r"(b[1]));
}

// ---------------------------------------------------------------------------
// tf32 mma.sync GEMM: C[M,N] = A[M,K] @ B[N,K]^T (+ epilogue)
// ---------------------------------------------------------------------------
#define BK  32
#define PAD 4

template <int EPI>
__global__ void __launch_bounds__(256) tc_gemm(const float* __restrict__ A,
                                               const float* __restrict__ B,
                                               float* __restrict__ C,
                                               const float* __restrict__ bias,
                                               const float* __restrict__ res,
                                               int M, int N, int K)
{
    __shared__ uint32_t As[128][BK + PAD];
    __shared__ uint32_t Bs[128][BK + PAD];

    const int tid  = threadIdx.x;
    const int wid  = tid >> 5;
    const int lane = tid & 31;
    const int warp_m = wid >> 2;
    const int warp_n = wid & 3;
    const int lr = lane >> 2;
    const int lc = lane & 3;

    const float* Ab = A + (size_t)blockIdx.y * 128 * K;
    const float* Bb = B + (size_t)blockIdx.x * 128 * K;

    float acc[16][4];
    #pragma unroll
    for (int i = 0; i < 16; i++)
        #pragma unroll
        for (int j = 0; j < 4; j++) acc[i][j] = 0.f;

    const int NC = K / BK;
    float4 pa[4], pb[4];

    #pragma unroll
    for (int i = 0; i < 4; i++) {
        int f = i * 256 + tid;
        int row = f >> 3, c4 = (f & 7) * 4;
        pa[i] = *(const float4*)(Ab + (size_t)row * K + c4);
        pb[i] = *(const float4*)(Bb + (size_t)row * K + c4);
    }

    for (int c = 0; c < NC; c++) {
        #pragma unroll
        for (int i = 0; i < 4; i++) {
            int f = i * 256 + tid;
            int row = f >> 3, c4 = (f & 7) * 4;
            As[row][c4 + 0] = f2tf(pa[i].x); As[row][c4 + 1] = f2tf(pa[i].y);
            As[row][c4 + 2] = f2tf(pa[i].z); As[row][c4 + 3] = f2tf(pa[i].w);
            Bs[row][c4 + 0] = f2tf(pb[i].x); Bs[row][c4 + 1] = f2tf(pb[i].y);
            Bs[row][c4 + 2] = f2tf(pb[i].z); Bs[row][c4 + 3] = f2tf(pb[i].w);
        }
        __syncthreads();

        if (c + 1 < NC) {
            const int k0 = (c + 1) * BK;
            #pragma unroll
            for (int i = 0; i < 4; i++) {
                int f = i * 256 + tid;
                int row = f >> 3, c4 = (f & 7) * 4;
                pa[i] = *(const float4*)(Ab + (size_t)row * K + k0 + c4);
                pb[i] = *(const float4*)(Bb + (size_t)row * K + k0 + c4);
            }
        }

        #pragma unroll
        for (int kk = 0; kk < BK; kk += 8) {
            uint32_t afr[4][4], bfr[4][2];
            #pragma unroll
            for (int mt = 0; mt < 4; mt++) {
                int ar = warp_m * 64 + mt * 16 + lr;
                afr[mt][0] = As[ar][kk + lc];
                afr[mt][1] = As[ar + 8][kk + lc];
                afr[mt][2] = As[ar][kk + lc + 4];
                afr[mt][3] = As[ar + 8][kk + lc + 4];
            }
            #pragma unroll
            for (int nt = 0; nt < 4; nt++) {
                int br = warp_n * 32 + nt * 8 + lr;
                bfr[nt][0] = Bs[br][kk + lc];
                bfr[nt][1] = Bs[br][kk + lc + 4];
            }
            #pragma unroll
            for (int mt = 0; mt < 4; mt++)
                #pragma unroll
                for (int nt = 0; nt < 4; nt++)
                    mma_tf32(acc[mt * 4 + nt], afr[mt], bfr[nt]);
        }
        __syncthreads();
    }

    #pragma unroll
    for (int mt = 0; mt < 4; mt++) {
        #pragma unroll
        for (int h = 0; h < 2; h++) {
            int row = blockIdx.y * 128 + warp_m * 64 + mt * 16 + lr + h * 8;
            float* Crow = C + (size_t)row * N;
            const float* Rrow = (EPI == 1 || EPI == 3) ? res + (size_t)row * N : nullptr;
            #pragma unroll
            for (int nt = 0; nt < 4; nt++) {
                int col = blockIdx.x * 128 + warp_n * 32 + nt * 8 + lc * 2;
                float v0 = acc[mt * 4 + nt][h * 2 + 0];
                float v1 = acc[mt * 4 + nt][h * 2 + 1];
                if (EPI == 2 || EPI == 3) {
                    v0 += bias[col];
                    v1 += bias[col + 1];
                }
                if (EPI == 2) {
                    v0 = 0.5f * v0 * (1.f + erff(v0 * 0.70710678118f));
                    v1 = 0.5f * v1 * (1.f + erff(v1 * 0.70710678118f));
                }
                if (EPI == 1 || EPI == 3) {
                    v0 += Rrow[col];
                    v1 += Rrow[col + 1];
                }
                *(float2*)(Crow + col) = make_float2(v0, v1);
            }
        }
    }
}

// ---------------------------------------------------------------------------
// LayerNorm
// ---------------------------------------------------------------------------
__global__ void __launch_bounds__(256) ln_kernel(const float* __restrict__ x,
                                                 const float* __restrict__ g,
                                                 const float* __restrict__ b,
                                                 float* __restrict__ out)
{
    int row = blockIdx.x;
    int t = threadIdx.x;
    const float4* xr = (const float4*)(x + (size_t)row * HDIM);
    float4 xv = xr[t];
    float s  = xv.x + xv.y + xv.z + xv.w;
    float ss = xv.x*xv.x + xv.y*xv.y + xv.z*xv.z + xv.w*xv.w;
    #pragma unroll
    for (int o = 16; o > 0; o >>= 1) {
        s  += __shfl_xor_sync(0xffffffffu, s,  o);
        ss += __shfl_xor_sync(0xffffffffu, ss, o);
    }
    __shared__ float sred[8], ssred[8];
    if ((t & 31) == 0) { sred[t >> 5] = s; ssred[t >> 5] = ss; }
    __syncthreads();
    if (t < 32) {
        float a  = (t < 8) ? sred[t]  : 0.f;
        float a2 = (t < 8) ? ssred[t] : 0.f;
        #pragma unroll
        for (int o = 4; o > 0; o >>= 1) {
            a  += __shfl_xor_sync(0xffffffffu, a,  o);
            a2 += __shfl_xor_sync(0xffffffffu, a2, o);
        }
        if (t == 0) { sred[0] = a; ssred[0] = a2; }
    }
    __syncthreads();
    float mean = sred[0] * (1.f / HDIM);
    float var  = ssred[0] * (1.f / HDIM) - mean * mean;
    float rstd = rsqrtf(var + 1e-5f);
    float4 gv = ((const float4*)g)[t];
    float4 bv = ((const float4*)b)[t];
    float4 ov;
    ov.x = (xv.x - mean) * rstd * gv.x + bv.x;
    ov.y = (xv.y - mean) * rstd * gv.y + bv.y;
    ov.z = (xv.z - mean) * rstd * gv.z + bv.z;
    ov.w = (xv.w - mean) * rstd * gv.w + bv.w;
    ((float4*)(out + (size_t)row * HDIM))[t] = ov;
}

// ---------------------------------------------------------------------------
// RoPE
// ---------------------------------------------------------------------------
__global__ void __launch_bounds__(256) rope_kernel(float* __restrict__ qkv,
                                                   const float* __restrict__ cosb,
                                                   const float* __restrict__ sinb)
{
    int idx = blockIdx.x * blockDim.x + threadIdx.x;
    int i    = idx & 31;
    int head = (idx >> 5) & 15;
    int qk   = (idx >> 9) & 1;
    int s    = idx >> 10;
    float c  = cosb[s * 32 + i];
    float sn = sinb[s * 32 + i];
    float2* p = (float2*)(qkv + (size_t)s * 3072 + qk * 1024 + head * 64 + 2 * i);
    float2 v = *p;
    float2 o;
    o.x = v.x * c - v.y * sn;
    o.y = v.x * sn + v.y * c;
    *p = o;
}

// ---------------------------------------------------------------------------
// Flash attention with m16n8k8 tf32 tensor cores.
// Block: one (seg, head, 128-query tile); 8 warps x 16 query rows.
// K-tiles of 64 keys; online softmax in fragments.
// smem (uint32 tf32): Qs[128][68], Ks[64][68], Vt[64][68]
// ---------------------------------------------------------------------------
#define SD 68
#define ATTN_SMEM ((128 + 64 + 64) * SD * 4)

__global__ void __launch_bounds__(256) fa_kernel(const float* __restrict__ qkv,
                                                 float* __restrict__ out)
{
    extern __shared__ uint32_t sm[];
    uint32_t* Qs = sm;                 // [128][SD]
    uint32_t* Ks = sm + 128 * SD;      // [64][SD]
    uint32_t* Vt = Ks + 64 * SD;       // [64][SD] (d-major: Vt[d][key])

    const int qt   = blockIdx.x;
    const int head = blockIdx.y;
    const int seg  = blockIdx.z;
    const int tid  = threadIdx.x;
    const int wid  = tid >> 5;
    const int lane = tid & 31;
    const int lr   = lane >> 2;
    const int lc   = lane & 3;

    const int qbase = seg * LSEG + qt * 128;
    const float* qp = qkv + (size_t)qbase * 3072 + head * 64;
    const float* kbase = qkv + (size_t)seg * LSEG * 3072 + 1024 + head * 64;
    const float* vbase = kbase + 1024;

    // Stage Q (scaled by 1/8) into smem: 128x64 -> 2048 float4, 8 per thread
    #pragma unroll
    for (int i = 0; i < 8; i++) {
        int f = i * 256 + tid;
        int row = f >> 4, c4 = (f & 15) * 4;
        float4 v = *(const float4*)(qp + (size_t)row * 3072 + c4);
        uint32_t* d = Qs + row * SD + c4;
        d[0] = f2tf(v.x * 0.125f); d[1] = f2tf(v.y * 0.125f);
        d[2] = f2tf(v.z * 0.125f); d[3] = f2tf(v.w * 0.125f);
    }
    __syncthreads();

    // Q fragments in registers: a[ks][4] for rows wid*16+lr, +8
    uint32_t aq[8][4];
    {
        const int qr = wid * 16 + lr;
        #pragma unroll
        for (int ks = 0; ks < 8; ks++) {
            aq[ks][0] = Qs[qr * SD + ks * 8 + lc];
            aq[ks][1] = Qs[(qr + 8) * SD + ks * 8 + lc];
            aq[ks][2] = Qs[qr * SD + ks * 8 + lc + 4];
            aq[ks][3] = Qs[(qr + 8) * SD + ks * 8 + lc + 4];
        }
    }

    float O[8][4];
    #pragma unroll
    for (int nt = 0; nt < 8; nt++)
        #pragma unroll
        for (int j = 0; j < 4; j++) O[nt][j] = 0.f;
    float m0 = -1e30f, m1 = -1e30f, l0 = 0.f, l1 = 0.f;

    for (int kt = 0; kt < 16; kt++) {
        __syncthreads();
        // Load K tile (64x64) and V tile transposed
        #pragma unroll
        for (int i = 0; i < 4; i++) {
            int f = i * 256 + tid;
            int key = f >> 4, c4 = (f & 15) * 4;
            float4 kv = *(const float4*)(kbase + (size_t)(kt * 64 + key) * 3072 + c4);
            uint32_t* d = Ks + key * SD + c4;
            d[0] = f2tf(kv.x); d[1] = f2tf(kv.y); d[2] = f2tf(kv.z); d[3] = f2tf(kv.w);
            float4 vv = *(const float4*)(vbase + (size_t)(kt * 64 + key) * 3072 + c4);
            Vt[(c4 + 0) * SD + key] = f2tf(vv.x);
            Vt[(c4 + 1) * SD + key] = f2tf(vv.y);
            Vt[(c4 + 2) * SD + key] = f2tf(vv.z);
            Vt[(c4 + 3) * SD + key] = f2tf(vv.w);
        }
        __syncthreads();

        // S = Q @ K^T : 8 n-tiles (keys), 8 k-steps (dim)
        float s[8][4];
        #pragma unroll
        for (int nt = 0; nt < 8; nt++) {
            s[nt][0] = s[nt][1] = s[nt][2] = s[nt][3] = 0.f;
            const uint32_t* kr = Ks + (nt * 8 + lr) * SD;
            #pragma unroll
            for (int ks = 0; ks < 8; ks++) {
                uint32_t b[2] = { kr[ks * 8 + lc], kr[ks * 8 + lc + 4] };
                mma_tf32(s[nt], aq[ks], b);
            }
        }

        // Online softmax
        float tm0 = -1e30f, tm1 = -1e30f;
        #pragma unroll
        for (int nt = 0; nt < 8; nt++) {
            tm0 = fmaxf(tm0, fmaxf(s[nt][0], s[nt][1]));
            tm1 = fmaxf(tm1, fmaxf(s[nt][2], s[nt][3]));
        }
        #pragma unroll
        for (int o = 1; o <= 2; o <<= 1) {
            tm0 = fmaxf(tm0, __shfl_xor_sync(0xffffffffu, tm0, o));
            tm1 = fmaxf(tm1, __shfl_xor_sync(0xffffffffu, tm1, o));
        }
        float mn0 = fmaxf(m0, tm0), mn1 = fmaxf(m1, tm1);
        float c0 = __expf(m0 - mn0), c1 = __expf(m1 - mn1);
        l0 *= c0; l1 *= c1;
        #pragma unroll
        for (int nt = 0; nt < 8; nt++) {
            O[nt][0] *= c0; O[nt][1] *= c0;
            O[nt][2] *= c1; O[nt][3] *= c1;
        }
        float ls0 = 0.f, ls1 = 0.f;
        #pragma unroll
        for (int nt = 0; nt < 8; nt++) {
            s[nt][0] = __expf(s[nt][0] - mn0);
            s[nt][1] = __expf(s[nt][1] - mn0);
            s[nt][2] = __expf(s[nt][2] - mn1);
            s[nt][3] = __expf(s[nt][3] - mn1);
            ls0 += s[nt][0] + s[nt][1];
            ls1 += s[nt][2] + s[nt][3];
        }
        #pragma unroll
        for (int o = 1; o <= 2; o <<= 1) {
            ls0 += __shfl_xor_sync(0xffffffffu, ls0, o);
            ls1 += __shfl_xor_sync(0xffffffffu, ls1, o);
        }
        l0 += ls0; l1 += ls1;
        m0 = mn0; m1 = mn1;

        // O += P @ V : rearrange P frag (accum layout -> A layout) via quad shfl
        const int base = lane & ~3;
        const int s0l = base + (lc >> 1);
        const int s1l = s0l + 2;
        #pragma unroll
        for (int ks = 0; ks < 8; ks++) {
            float v0 = __shfl_sync(0xffffffffu, s[ks][0], s0l);
            float v1 = __shfl_sync(0xffffffffu, s[ks][1], s0l);
            float v2 = __shfl_sync(0xffffffffu, s[ks][2], s0l);
            float v3 = __shfl_sync(0xffffffffu, s[ks][3], s0l);
            float w0 = __shfl_sync(0xffffffffu, s[ks][0], s1l);
            float w1 = __shfl_sync(0xffffffffu, s[ks][1], s1l);
            float w2 = __shfl_sync(0xffffffffu, s[ks][2], s1l);
            float w3 = __shfl_sync(0xffffffffu, s[ks][3], s1l);
            bool odd = lc & 1;
            uint32_t a[4];
            a[0] = f2tf(odd ? v1 : v0);
            a[1] = f2tf(odd ? v3 : v2);
            a[2] = f2tf(odd ? w1 : w0);
            a[3] = f2tf(odd ? w3 : w2);
            #pragma unroll
            for (int nt = 0; nt < 8; nt++) {
                const uint32_t* vr = Vt + (nt * 8 + lr) * SD;
                uint32_t b[2] = { vr[ks * 8 + lc], vr[ks * 8 + lc + 4] };
                mma_tf32(O[nt], a, b);
            }
        }
    }

    // Write output
    float inv0 = 1.f / l0, inv1 = 1.f / l1;
    const int row0 = qbase + wid * 16 + lr;
    float* o0 = out + (size_t)row0 * HDIM + head * 64;
    float* o1 = o0 + 8 * HDIM;
    #pragma unroll
    for (int nt = 0; nt < 8; nt++) {
        *(float2*)(o0 + nt * 8 + lc * 2) = make_float2(O[nt][0] * inv0, O[nt][1] * inv0);
        *(float2*)(o1 + nt * 8 + lc * 2) = make_float2(O[nt][2] * inv1, O[nt][3] * inv1);
    }
}

// ---------------------------------------------------------------------------
extern "C" void kernel_launch(void* const* d_in, const int* in_sizes, int n_in,
                              void* d_out, int out_size)
{
    const float* x        = (const float*)d_in[0];
    const float* wqkv     = (const float*)d_in[1];
    const float* wo       = (const float*)d_in[2];
    const float* ln0_g    = (const float*)d_in[3];
    const float* ln0_b    = (const float*)d_in[4];
    const float* ln1_g    = (const float*)d_in[5];
    const float* ln1_b    = (const float*)d_in[6];
    const float* fc0_w    = (const float*)d_in[7];
    const float* fc0_b    = (const float*)d_in[8];
    const float* fc1_w    = (const float*)d_in[9];
    const float* fc1_b    = (const float*)d_in[10];
    const float* rope_cos = (const float*)d_in[11];
    const float* rope_sin = (const float*)d_in[12];
    float* out = (float*)d_out;

    float *h, *qkv, *attn, *x1, *h2, *mid;
    cudaGetSymbolAddress((void**)&h,    g_h);
    cudaGetSymbolAddress((void**)&qkv,  g_qkv);
    cudaGetSymbolAddress((void**)&attn, g_attn);
    cudaGetSymbolAddress((void**)&x1,   g_x1);
    cudaGetSymbolAddress((void**)&h2,   g_h2);
    cudaGetSymbolAddress((void**)&mid,  g_mid);

    cudaFuncSetAttribute(fa_kernel, cudaFuncAttributeMaxDynamicSharedMemorySize, ATTN_SMEM);

    // 1. ln0
    ln_kernel<<<S_TOK, 256>>>(x, ln0_g, ln0_b, h);
    // 2. qkv = h @ wqkv^T
    tc_gemm<0><<<dim3(3 * HDIM / 128, S_TOK / 128), 256>>>(h, wqkv, qkv, nullptr, nullptr,
                                                           S_TOK, 3 * HDIM, HDIM);
    // 3. rope(q), rope(k)
    rope_kernel<<<(S_TOK * 2 * NHEAD * 32) / 256, 256>>>(qkv, rope_cos, rope_sin);
    // 4. attention (tensor-core flash)
    fa_kernel<<<dim3(LSEG / 128, NHEAD, NSEG), 256, ATTN_SMEM>>>(qkv, attn);
    // 5. x1 = x + attn @ wo^T
    tc_gemm<1><<<dim3(HDIM / 128, S_TOK / 128), 256>>>(attn, wo, x1, nullptr, x,
                                                       S_TOK, HDIM, HDIM);
    // 6. ln1
    ln_kernel<<<S_TOK, 256>>>(x1, ln1_g, ln1_b, h2);
    // 7. mid = gelu(h2 @ fc0_w^T + b)
    tc_gemm<2><<<dim3(MLPD / 128, S_TOK / 128), 256>>>(h2, fc0_w, mid, fc0_b, nullptr,
                                                       S_TOK, MLPD, HDIM);
    // 8. out = x1 + mid @ fc1_w^T + b
    tc_gemm<3><<<dim3(HDIM / 128, S_TOK / 128), 256>>>(mid, fc1_w, out, fc1_b, x1,
                                                       S_TOK, HDIM, MLPD);
}

// round 5
// speedup vs baseline: 3.6047x; 1.2842x over previous
#include <cuda_runtime.h>
#include <math.h>
#include <stdint.h>

// Problem constants
#define S_TOK   8192
#define HDIM    1024
#define NHEAD   16
#define HD      64
#define MLPD    4096
#define NSEG    8
#define LSEG    1024

// Scratch buffers (tf32 values stored as uint32 where noted)
__device__ uint32_t g_h   [S_TOK * HDIM];     // ln0 out (tf32)
__device__ float    g_qkv [S_TOK * 3 * HDIM]; // f32 (rope applied in epilogue)
__device__ uint32_t g_attn[S_TOK * HDIM];     // fa out (tf32)
__device__ float    g_x1  [S_TOK * HDIM];     // f32
__device__ uint32_t g_h2  [S_TOK * HDIM];     // ln1 out (tf32)
__device__ uint32_t g_mid [S_TOK * MLPD];     // gelu(fc0) (tf32)
// pre-converted weights (tf32)
__device__ uint32_t g_wqkv_t[3 * HDIM * HDIM];
__device__ uint32_t g_wo_t  [HDIM * HDIM];
__device__ uint32_t g_fc0_t [MLPD * HDIM];
__device__ uint32_t g_fc1_t [HDIM * MLPD];

__device__ __forceinline__ uint32_t f2tf(float x) {
    uint32_t r;
    asm("cvt.rna.tf32.f32 %0, %1;" : "=r"(r) : "f"(x));
    return r;
}
__device__ __forceinline__ uint32_t smem_u32(const void* p) {
    uint32_t a;
    asm("{ .reg .u64 t; cvta.to.shared.u64 t, %1; cvt.u32.u64 %0, t; }" : "=r"(a) : "l"(p));
    return a;
}
__device__ __forceinline__ void mma_tf32(float* d, const uint32_t* a, const uint32_t* b) {
    asm volatile(
        "mma.sync.aligned.m16n8k8.row.col.f32.tf32.tf32.f32 "
        "{%0,%1,%2,%3}, {%4,%5,%6,%7}, {%8,%9}, {%0,%1,%2,%3};"
        : "+f"(d[0]), "+f"(d[1]), "+f"(d[2]), "+f"(d[3])
        : "r"(a[0]), "r"(a[1]), "r"(a[2]), "r"(a[3]), "r"(b[0]), "r"(b[1]));
}
__device__ __forceinline__ void ldm4(uint32_t* r, uint32_t addr) {
    asm volatile("ldmatrix.sync.aligned.m8n8.x4.shared.b16 {%0,%1,%2,%3}, [%4];"
                 : "=r"(r[0]), "=r"(r[1]), "=r"(r[2]), "=r"(r[3]) : "r"(addr));
}
__device__ __forceinline__ void cp16(uint32_t dst, const void* src) {
    asm volatile("cp.async.cg.shared.global [%0], [%1], 16;" :: "r"(dst), "l"(src) : "memory");
}

// ---------------------------------------------------------------------------
// tf32 mma.sync GEMM, cp.async double-buffered, ldmatrix fragments.
// C[M,N] = A[M,K] @ B[N,K]^T (+ epilogue). A,B already tf32 (uint32).
// 128x128 tile, BK=32, 256 threads, 64x32 warp tile.
// EPI: 1=+res, 2=+bias+GELU, 3=+bias+res, 4=rope(q,k cols<2048)
// OUTTF: 1 -> write tf32 (uint32), 0 -> write f32
// ---------------------------------------------------------------------------
#define STRD 36
#define GEMM_SMEM (4 * 128 * STRD * 4)

template <int EPI, int OUTTF>
__global__ void __launch_bounds__(256, 2)
tc_gemm(const uint32_t* __restrict__ A, const uint32_t* __restrict__ B,
        void* __restrict__ Cv, const float* __restrict__ bias,
        const float* __restrict__ res,
        const float* __restrict__ cosb, const float* __restrict__ sinb,
        int M, int N, int K)
{
    extern __shared__ uint32_t sm4[];
    const uint32_t smb = smem_u32(sm4);

    const int tid  = threadIdx.x;
    const int wid  = tid >> 5;
    const int lane = tid & 31;
    const int warp_m = wid >> 2;
    const int warp_n = wid & 3;
    const int lr = lane >> 2;
    const int lc = lane & 3;

    const uint32_t* Ab = A + (size_t)blockIdx.y * 128 * K;
    const uint32_t* Bb = B + (size_t)blockIdx.x * 128 * K;

    // loader: thread covers 4x 16B chunks per matrix
    const int ldrow = tid >> 1;               // f>>3 pattern below
    float acc[16][4];
    #pragma unroll
    for (int i = 0; i < 16; i++)
        #pragma unroll
        for (int j = 0; j < 4; j++) acc[i][j] = 0.f;

    const int NC = K >> 5;

    // per-thread fragment base addresses (byte)
    const uint32_t aFragBase = smb + ((warp_m * 64 + (lane & 15)) * STRD +
                                      ((lane >> 4) & 1) * 4) * 4;
    const uint32_t bFragBase = smb + (128 * STRD) * 4 +
                               ((warp_n * 32 + (lane & 7) + ((lane >> 4) & 1) * 8) * STRD +
                                ((lane >> 3) & 1) * 4) * 4;
    const uint32_t BUFSTEP = 2 * 128 * STRD * 4;   // bytes per (A,B) pair

    // issue chunk c into buffer b
    auto issue = [&](int c, int b) {
        const int k0 = c << 5;
        #pragma unroll
        for (int i = 0; i < 4; i++) {
            int f = i * 256 + tid;
            int row = f >> 3, c4 = (f & 7) * 4;
            uint32_t da = smb + (uint32_t)b * BUFSTEP + (row * STRD + c4) * 4;
            uint32_t db = da + 128 * STRD * 4;
            cp16(da, Ab + (size_t)row * K + k0 + c4);
            cp16(db, Bb + (size_t)row * K + k0 + c4);
        }
        asm volatile("cp.async.commit_group;" ::: "memory");
    };

    issue(0, 0);

    for (int c = 0; c < NC; c++) {
        const int b = c & 1;
        if (c + 1 < NC) {
            issue(c + 1, b ^ 1);
            asm volatile("cp.async.wait_group 1;" ::: "memory");
        } else {
            asm volatile("cp.async.wait_group 0;" ::: "memory");
        }
        __syncthreads();

        const uint32_t aB = aFragBase + (uint32_t)b * BUFSTEP;
        const uint32_t bB = bFragBase + (uint32_t)b * BUFSTEP;
        #pragma unroll
        for (int kk = 0; kk < 4; kk++) {
            uint32_t afr[4][4], bfr[4][2];
            #pragma unroll
            for (int mt = 0; mt < 4; mt++)
                ldm4(afr[mt], aB + (mt * 16 * STRD + kk * 8) * 4);
            #pragma unroll
            for (int g = 0; g < 2; g++) {
                uint32_t t[4];
                ldm4(t, bB + (g * 16 * STRD + kk * 8) * 4);
                bfr[2 * g][0] = t[0]; bfr[2 * g][1] = t[1];
                bfr[2 * g + 1][0] = t[2]; bfr[2 * g + 1][1] = t[3];
            }
            #pragma unroll
            for (int mt = 0; mt < 4; mt++)
                #pragma unroll
                for (int nt = 0; nt < 4; nt++)
                    mma_tf32(acc[mt * 4 + nt], afr[mt], bfr[nt]);
        }
        __syncthreads();
    }

    // Epilogue
    #pragma unroll
    for (int mt = 0; mt < 4; mt++) {
        #pragma unroll
        for (int h = 0; h < 2; h++) {
            int row = blockIdx.y * 128 + warp_m * 64 + mt * 16 + lr + h * 8;
            #pragma unroll
            for (int nt = 0; nt < 4; nt++) {
                int col = blockIdx.x * 128 + warp_n * 32 + nt * 8 + lc * 2;
                float v0 = acc[mt * 4 + nt][h * 2 + 0];
                float v1 = acc[mt * 4 + nt][h * 2 + 1];
                if (EPI == 2 || EPI == 3) {
                    v0 += bias[col];
                    v1 += bias[col + 1];
                }
                if (EPI == 2) {
                    v0 = 0.5f * v0 * (1.f + erff(v0 * 0.70710678118f));
                    v1 = 0.5f * v1 * (1.f + erff(v1 * 0.70710678118f));
                }
                if (EPI == 1 || EPI == 3) {
                    v0 += res[(size_t)row * N + col];
                    v1 += res[(size_t)row * N + col + 1];
                }
                if (EPI == 4) {
                    if (col < 2048) {
                        int i = (col & 63) >> 1;
                        float cc = cosb[row * 32 + i];
                        float ss = sinb[row * 32 + i];
                        float o0 = v0 * cc - v1 * ss;
                        float o1 = v0 * ss + v1 * cc;
                        v0 = o0; v1 = o1;
                    }
                }
                if (OUTTF) {
                    uint2 u = make_uint2(f2tf(v0), f2tf(v1));
                    *(uint2*)((uint32_t*)Cv + (size_t)row * N + col) = u;
                } else {
                    *(float2*)((float*)Cv + (size_t)row * N + col) = make_float2(v0, v1);
                }
            }
        }
    }
}

// ---------------------------------------------------------------------------
// Weight convert f32 -> tf32
// ---------------------------------------------------------------------------
__global__ void __launch_bounds__(256) cvt_kernel(const float* __restrict__ src,
                                                  uint32_t* __restrict__ dst)
{
    int i = blockIdx.x * 256 + threadIdx.x;
    float4 v = ((const float4*)src)[i];
    uint4 u = make_uint4(f2tf(v.x), f2tf(v.y), f2tf(v.z), f2tf(v.w));
    ((uint4*)dst)[i] = u;
}

// ---------------------------------------------------------------------------
// LayerNorm: writes tf32 (uint32)
// ---------------------------------------------------------------------------
__global__ void __launch_bounds__(256) ln_kernel(const float* __restrict__ x,
                                                 const float* __restrict__ g,
                                                 const float* __restrict__ b,
                                                 uint32_t* __restrict__ out)
{
    int row = blockIdx.x;
    int t = threadIdx.x;
    const float4* xr = (const float4*)(x + (size_t)row * HDIM);
    float4 xv = xr[t];
    float s  = xv.x + xv.y + xv.z + xv.w;
    float ss = xv.x*xv.x + xv.y*xv.y + xv.z*xv.z + xv.w*xv.w;
    #pragma unroll
    for (int o = 16; o > 0; o >>= 1) {
        s  += __shfl_xor_sync(0xffffffffu, s,  o);
        ss += __shfl_xor_sync(0xffffffffu, ss, o);
    }
    __shared__ float sred[8], ssred[8];
    if ((t & 31) == 0) { sred[t >> 5] = s; ssred[t >> 5] = ss; }
    __syncthreads();
    if (t < 32) {
        float a  = (t < 8) ? sred[t]  : 0.f;
        float a2 = (t < 8) ? ssred[t] : 0.f;
        #pragma unroll
        for (int o = 4; o > 0; o >>= 1) {
            a  += __shfl_xor_sync(0xffffffffu, a,  o);
            a2 += __shfl_xor_sync(0xffffffffu, a2, o);
        }
        if (t == 0) { sred[0] = a; ssred[0] = a2; }
    }
    __syncthreads();
    float mean = sred[0] * (1.f / HDIM);
    float var  = ssred[0] * (1.f / HDIM) - mean * mean;
    float rstd = rsqrtf(var + 1e-5f);
    float4 gv = ((const float4*)g)[t];
    float4 bv = ((const float4*)b)[t];
    uint4 ov;
    ov.x = f2tf((xv.x - mean) * rstd * gv.x + bv.x);
    ov.y = f2tf((xv.y - mean) * rstd * gv.y + bv.y);
    ov.z = f2tf((xv.z - mean) * rstd * gv.z + bv.z);
    ov.w = f2tf((xv.w - mean) * rstd * gv.w + bv.w);
    ((uint4*)(out + (size_t)row * HDIM))[t] = ov;
}

// ---------------------------------------------------------------------------
// Flash attention, m16n8k8 tf32; writes attn as tf32 (uint32)
// ---------------------------------------------------------------------------
#define SD 68
#define ATTN_SMEM ((128 + 64 + 64) * SD * 4)

__global__ void __launch_bounds__(256) fa_kernel(const float* __restrict__ qkv,
                                                 uint32_t* __restrict__ out)
{
    extern __shared__ uint32_t sm[];
    uint32_t* Qs = sm;
    uint32_t* Ks = sm + 128 * SD;
    uint32_t* Vt = Ks + 64 * SD;

    const int qt   = blockIdx.x;
    const int head = blockIdx.y;
    const int seg  = blockIdx.z;
    const int tid  = threadIdx.x;
    const int wid  = tid >> 5;
    const int lane = tid & 31;
    const int lr   = lane >> 2;
    const int lc   = lane & 3;

    const int qbase = seg * LSEG + qt * 128;
    const float* qp = qkv + (size_t)qbase * 3072 + head * 64;
    const float* kbase = qkv + (size_t)seg * LSEG * 3072 + 1024 + head * 64;
    const float* vbase = kbase + 1024;

    #pragma unroll
    for (int i = 0; i < 8; i++) {
        int f = i * 256 + tid;
        int row = f >> 4, c4 = (f & 15) * 4;
        float4 v = *(const float4*)(qp + (size_t)row * 3072 + c4);
        uint32_t* d = Qs + row * SD + c4;
        d[0] = f2tf(v.x * 0.125f); d[1] = f2tf(v.y * 0.125f);
        d[2] = f2tf(v.z * 0.125f); d[3] = f2tf(v.w * 0.125f);
    }
    __syncthreads();

    uint32_t aq[8][4];
    {
        const int qr = wid * 16 + lr;
        #pragma unroll
        for (int ks = 0; ks < 8; ks++) {
            aq[ks][0] = Qs[qr * SD + ks * 8 + lc];
            aq[ks][1] = Qs[(qr + 8) * SD + ks * 8 + lc];
            aq[ks][2] = Qs[qr * SD + ks * 8 + lc + 4];
            aq[ks][3] = Qs[(qr + 8) * SD + ks * 8 + lc + 4];
        }
    }

    float O[8][4];
    #pragma unroll
    for (int nt = 0; nt < 8; nt++)
        #pragma unroll
        for (int j = 0; j < 4; j++) O[nt][j] = 0.f;
    float m0 = -1e30f, m1 = -1e30f, l0 = 0.f, l1 = 0.f;

    for (int kt = 0; kt < 16; kt++) {
        __syncthreads();
        #pragma unroll
        for (int i = 0; i < 4; i++) {
            int f = i * 256 + tid;
            int key = f >> 4, c4 = (f & 15) * 4;
            float4 kv = *(const float4*)(kbase + (size_t)(kt * 64 + key) * 3072 + c4);
            uint32_t* d = Ks + key * SD + c4;
            d[0] = f2tf(kv.x); d[1] = f2tf(kv.y); d[2] = f2tf(kv.z); d[3] = f2tf(kv.w);
            float4 vv = *(const float4*)(vbase + (size_t)(kt * 64 + key) * 3072 + c4);
            Vt[(c4 + 0) * SD + key] = f2tf(vv.x);
            Vt[(c4 + 1) * SD + key] = f2tf(vv.y);
            Vt[(c4 + 2) * SD + key] = f2tf(vv.z);
            Vt[(c4 + 3) * SD + key] = f2tf(vv.w);
        }
        __syncthreads();

        float s[8][4];
        #pragma unroll
        for (int nt = 0; nt < 8; nt++) {
            s[nt][0] = s[nt][1] = s[nt][2] = s[nt][3] = 0.f;
            const uint32_t* kr = Ks + (nt * 8 + lr) * SD;
            #pragma unroll
            for (int ks = 0; ks < 8; ks++) {
                uint32_t b[2] = { kr[ks * 8 + lc], kr[ks * 8 + lc + 4] };
                mma_tf32(s[nt], aq[ks], b);
            }
        }

        float tm0 = -1e30f, tm1 = -1e30f;
        #pragma unroll
        for (int nt = 0; nt < 8; nt++) {
            tm0 = fmaxf(tm0, fmaxf(s[nt][0], s[nt][1]));
            tm1 = fmaxf(tm1, fmaxf(s[nt][2], s[nt][3]));
        }
        #pragma unroll
        for (int o = 1; o <= 2; o <<= 1) {
            tm0 = fmaxf(tm0, __shfl_xor_sync(0xffffffffu, tm0, o));
            tm1 = fmaxf(tm1, __shfl_xor_sync(0xffffffffu, tm1, o));
        }
        float mn0 = fmaxf(m0, tm0), mn1 = fmaxf(m1, tm1);
        float c0 = __expf(m0 - mn0), c1 = __expf(m1 - mn1);
        l0 *= c0; l1 *= c1;
        #pragma unroll
        for (int nt = 0; nt < 8; nt++) {
            O[nt][0] *= c0; O[nt][1] *= c0;
            O[nt][2] *= c1; O[nt][3] *= c1;
        }
        float ls0 = 0.f, ls1 = 0.f;
        #pragma unroll
        for (int nt = 0; nt < 8; nt++) {
            s[nt][0] = __expf(s[nt][0] - mn0);
            s[nt][1] = __expf(s[nt][1] - mn0);
            s[nt][2] = __expf(s[nt][2] - mn1);
            s[nt][3] = __expf(s[nt][3] - mn1);
            ls0 += s[nt][0] + s[nt][1];
            ls1 += s[nt][2] + s[nt][3];
        }
        #pragma unroll
        for (int o = 1; o <= 2; o <<= 1) {
            ls0 += __shfl_xor_sync(0xffffffffu, ls0, o);
            ls1 += __shfl_xor_sync(0xffffffffu, ls1, o);
        }
        l0 += ls0; l1 += ls1;
        m0 = mn0; m1 = mn1;

        const int base = lane & ~3;
        const int s0l = base + (lc >> 1);
        const int s1l = s0l + 2;
        #pragma unroll
        for (int ks = 0; ks < 8; ks++) {
            float v0 = __shfl_sync(0xffffffffu, s[ks][0], s0l);
            float v1 = __shfl_sync(0xffffffffu, s[ks][1], s0l);
            float v2 = __shfl_sync(0xffffffffu, s[ks][2], s0l);
            float v3 = __shfl_sync(0xffffffffu, s[ks][3], s0l);
            float w0 = __shfl_sync(0xffffffffu, s[ks][0], s1l);
            float w1 = __shfl_sync(0xffffffffu, s[ks][1], s1l);
            float w2 = __shfl_sync(0xffffffffu, s[ks][2], s1l);
            float w3 = __shfl_sync(0xffffffffu, s[ks][3], s1l);
            bool odd = lc & 1;
            uint32_t a[4];
            a[0] = f2tf(odd ? v1 : v0);
            a[1] = f2tf(odd ? v3 : v2);
            a[2] = f2tf(odd ? w1 : w0);
            a[3] = f2tf(odd ? w3 : w2);
            #pragma unroll
            for (int nt = 0; nt < 8; nt++) {
                const uint32_t* vr = Vt + (nt * 8 + lr) * SD;
                uint32_t b[2] = { vr[ks * 8 + lc], vr[ks * 8 + lc + 4] };
                mma_tf32(O[nt], a, b);
            }
        }
    }

    float inv0 = 1.f / l0, inv1 = 1.f / l1;
    const int row0 = qbase + wid * 16 + lr;
    uint32_t* o0 = out + (size_t)row0 * HDIM + head * 64;
    uint32_t* o1 = o0 + 8 * HDIM;
    #pragma unroll
    for (int nt = 0; nt < 8; nt++) {
        *(uint2*)(o0 + nt * 8 + lc * 2) =
            make_uint2(f2tf(O[nt][0] * inv0), f2tf(O[nt][1] * inv0));
        *(uint2*)(o1 + nt * 8 + lc * 2) =
            make_uint2(f2tf(O[nt][2] * inv1), f2tf(O[nt][3] * inv1));
    }
}

// ---------------------------------------------------------------------------
extern "C" void kernel_launch(void* const* d_in, const int* in_sizes, int n_in,
                              void* d_out, int out_size)
{
    const float* x        = (const float*)d_in[0];
    const float* wqkv     = (const float*)d_in[1];
    const float* wo       = (const float*)d_in[2];
    const float* ln0_g    = (const float*)d_in[3];
    const float* ln0_b    = (const float*)d_in[4];
    const float* ln1_g    = (const float*)d_in[5];
    const float* ln1_b    = (const float*)d_in[6];
    const float* fc0_w    = (const float*)d_in[7];
    const float* fc0_b    = (const float*)d_in[8];
    const float* fc1_w    = (const float*)d_in[9];
    const float* fc1_b    = (const float*)d_in[10];
    const float* rope_cos = (const float*)d_in[11];
    const float* rope_sin = (const float*)d_in[12];
    float* out = (float*)d_out;

    uint32_t *h, *attn, *h2, *mid, *wqkv_t, *wo_t, *fc0_t, *fc1_t;
    float *qkv, *x1;
    cudaGetSymbolAddress((void**)&h,      g_h);
    cudaGetSymbolAddress((void**)&qkv,    g_qkv);
    cudaGetSymbolAddress((void**)&attn,   g_attn);
    cudaGetSymbolAddress((void**)&x1,     g_x1);
    cudaGetSymbolAddress((void**)&h2,     g_h2);
    cudaGetSymbolAddress((void**)&mid,    g_mid);
    cudaGetSymbolAddress((void**)&wqkv_t, g_wqkv_t);
    cudaGetSymbolAddress((void**)&wo_t,   g_wo_t);
    cudaGetSymbolAddress((void**)&fc0_t,  g_fc0_t);
    cudaGetSymbolAddress((void**)&fc1_t,  g_fc1_t);

    cudaFuncSetAttribute(fa_kernel, cudaFuncAttributeMaxDynamicSharedMemorySize, ATTN_SMEM);
    cudaFuncSetAttribute(tc_gemm<4,0>, cudaFuncAttributeMaxDynamicSharedMemorySize, GEMM_SMEM);
    cudaFuncSetAttribute(tc_gemm<1,0>, cudaFuncAttributeMaxDynamicSharedMemorySize, GEMM_SMEM);
    cudaFuncSetAttribute(tc_gemm<2,1>, cudaFuncAttributeMaxDynamicSharedMemorySize, GEMM_SMEM);
    cudaFuncSetAttribute(tc_gemm<3,0>, cudaFuncAttributeMaxDynamicSharedMemorySize, GEMM_SMEM);

    // 0. weight converts (idempotent)
    cvt_kernel<<<(3 * HDIM * HDIM) / 1024, 256>>>(wqkv, wqkv_t);
    cvt_kernel<<<(HDIM * HDIM) / 1024, 256>>>(wo, wo_t);
    cvt_kernel<<<(MLPD * HDIM) / 1024, 256>>>(fc0_w, fc0_t);
    cvt_kernel<<<(HDIM * MLPD) / 1024, 256>>>(fc1_w, fc1_t);

    // 1. ln0 -> tf32
    ln_kernel<<<S_TOK, 256>>>(x, ln0_g, ln0_b, h);
    // 2. qkv = h @ wqkv^T with fused rope
    tc_gemm<4,0><<<dim3(3 * HDIM / 128, S_TOK / 128), 256, GEMM_SMEM>>>(
        h, wqkv_t, qkv, nullptr, nullptr, rope_cos, rope_sin, S_TOK, 3 * HDIM, HDIM);
    // 3. attention -> tf32
    fa_kernel<<<dim3(LSEG / 128, NHEAD, NSEG), 256, ATTN_SMEM>>>(qkv, attn);
    // 4. x1 = x + attn @ wo^T
    tc_gemm<1,0><<<dim3(HDIM / 128, S_TOK / 128), 256, GEMM_SMEM>>>(
        attn, wo_t, x1, nullptr, x, nullptr, nullptr, S_TOK, HDIM, HDIM);
    // 5. ln1 -> tf32
    ln_kernel<<<S_TOK, 256>>>(x1, ln1_g, ln1_b, h2);
    // 6. mid = gelu(h2 @ fc0^T + b) -> tf32
    tc_gemm<2,1><<<dim3(MLPD / 128, S_TOK / 128), 256, GEMM_SMEM>>>(
        h2, fc0_t, mid, fc0_b, nullptr, nullptr, nullptr, S_TOK, MLPD, HDIM);
    // 7. out = x1 + mid @ fc1^T + b
    tc_gemm<3,0><<<dim3(HDIM / 128, S_TOK / 128), 256, GEMM_SMEM>>>(
        mid, fc1_t, out, fc1_b, x1, nullptr, nullptr, S_TOK, HDIM, MLPD);
}